// round 10
// baseline (speedup 1.0000x reference)
#include <cuda_runtime.h>
#include <cuda_fp16.h>

#define N_NODES 100000
#define N_EDGES 3200000
#define D 128

#define SCAN_BLK 1024
#define NSCAN_BLKS ((N_NODES + SCAN_BLK - 1) / SCAN_BLK)   // 98

// smem row stride for GEMM tiles: 128 + 8 halves = 272B -> LDSM conflict-free
#define SROW 136
#define GEMM_SMEM_BYTES (2 * 128 * SROW * sizeof(__half))   // 69632

// ---------------- scratch (device globals; no allocation allowed) ----------
__device__ __half          g_h[(size_t)N_NODES * D];  // 25.6 MB h (fp16)
__device__ int             g_deg[N_NODES];
__device__ int             g_off[N_NODES];
__device__ int             g_bsum[NSCAN_BLKS];
__device__ unsigned short  g_epos[N_EDGES];           // position within row
__device__ int2            g_epair[N_EDGES];          // {col, val bits} grouped by row

__device__ __forceinline__ unsigned f2h2(float lo, float hi) {
    __half2 h = __floats2half2_rn(lo, hi);
    return *reinterpret_cast<unsigned*>(&h);
}

#define LDSM_X4(r0, r1, r2, r3, addr)                                         \
    asm volatile("ldmatrix.sync.aligned.m8n8.x4.shared.b16 {%0,%1,%2,%3}, [%4];" \
                 : "=r"(r0), "=r"(r1), "=r"(r2), "=r"(r3) : "r"(addr))

// ---------------------------------------------------------------------------
// Tensor-core GEMM: h[n][o] = sum_k x[n][k] * W[o][k]
// x and W staged (and fp32->fp16 converted) into padded smem once; fragments
// via ldmatrix.x4; mma.sync.m16n8k16 row.col, fp32 accum.
// Block: 128 thr = 4 warps along M; block tile 128x128, K=128 (one shot).
// ---------------------------------------------------------------------------
__global__ __launch_bounds__(128) void gemm_tc_kernel(const float* __restrict__ x,
                                                      const float* __restrict__ W) {
    extern __shared__ __half smem[];
    __half* sA = smem;                 // 128 x SROW
    __half* sB = smem + 128 * SROW;    // 128 x SROW

    const int t    = threadIdx.x;
    const int wid  = t >> 5;
    const int lane = t & 31;

    // ---- stage x and W: 4 threads per row, 32 rows per pass, 4 passes ----
#pragma unroll
    for (int pass = 0; pass < 4; pass++) {
        int r     = pass * 32 + (t >> 2);
        int cbase = (t & 3) * 32;
        int gr = blockIdx.x * 128 + r;
        if (gr >= N_NODES) gr = N_NODES - 1;       // clamp; stores masked later
        const float4* xs = (const float4*)&x[(size_t)gr * D + cbase];
        const float4* ws = (const float4*)&W[(size_t)r * D + cbase];
        __half2* xd = (__half2*)&sA[r * SROW + cbase];
        __half2* wd = (__half2*)&sB[r * SROW + cbase];
#pragma unroll
        for (int j = 0; j < 8; j++) {
            float4 v = xs[j];
            xd[j * 2]     = __floats2half2_rn(v.x, v.y);
            xd[j * 2 + 1] = __floats2half2_rn(v.z, v.w);
            float4 w = ws[j];
            wd[j * 2]     = __floats2half2_rn(w.x, w.y);
            wd[j * 2 + 1] = __floats2half2_rn(w.z, w.w);
        }
    }
    __syncthreads();

    float acc[2][16][4];
#pragma unroll
    for (int mt = 0; mt < 2; mt++)
#pragma unroll
        for (int nt = 0; nt < 16; nt++)
#pragma unroll
            for (int i = 0; i < 4; i++) acc[mt][nt][i] = 0.f;

    // ldmatrix lane->address mapping
    // A (.x4, m16k16): mat0 rows m0-7/k0-7, mat1 m8-15/k0-7, mat2 m0-7/k8-15, mat3 m8-15/k8-15
    const int a_row  = wid * 32 + (lane & 7) + ((lane >> 3) & 1) * 8; // +mt*16
    const int a_kofs = (lane >> 4) * 8;
    // B (.x4 = two n8k16 frags): mat0 ntA/k0-7, mat1 ntA/k8-15, mat2 ntB/k0-7, mat3 ntB/k8-15
    const int b_row  = (lane & 7) + (lane >> 4) * 8;                  // +p*16
    const int b_kofs = ((lane >> 3) & 1) * 8;

    unsigned aA[2];
#pragma unroll
    for (int mt = 0; mt < 2; mt++)
        aA[mt] = (unsigned)__cvta_generic_to_shared(
            &sA[(a_row + mt * 16) * SROW + a_kofs]);
    unsigned aB[8];
#pragma unroll
    for (int p = 0; p < 8; p++)
        aB[p] = (unsigned)__cvta_generic_to_shared(
            &sB[(b_row + p * 16) * SROW + b_kofs]);

#pragma unroll
    for (int ks = 0; ks < 8; ks++) {
        const unsigned ko = ks * 16 * sizeof(__half);   // byte offset along k

        unsigned a[2][4];
#pragma unroll
        for (int mt = 0; mt < 2; mt++)
            LDSM_X4(a[mt][0], a[mt][1], a[mt][2], a[mt][3], aA[mt] + ko);

        unsigned b[16][2];
#pragma unroll
        for (int p = 0; p < 8; p++)
            LDSM_X4(b[2 * p][0], b[2 * p][1], b[2 * p + 1][0], b[2 * p + 1][1],
                    aB[p] + ko);

#pragma unroll
        for (int nt = 0; nt < 16; nt++)
#pragma unroll
            for (int mt = 0; mt < 2; mt++) {
                asm volatile(
                    "mma.sync.aligned.m16n8k16.row.col.f32.f16.f16.f32 "
                    "{%0,%1,%2,%3}, {%4,%5,%6,%7}, {%8,%9}, {%0,%1,%2,%3};\n"
                    : "+f"(acc[mt][nt][0]), "+f"(acc[mt][nt][1]),
                      "+f"(acc[mt][nt][2]), "+f"(acc[mt][nt][3])
                    : "r"(a[mt][0]), "r"(a[mt][1]), "r"(a[mt][2]), "r"(a[mt][3]),
                      "r"(b[nt][0]), "r"(b[nt][1]));
            }
    }

    // Store h as fp16. D frag: d0,d1:(m=g, n=tc,tc+1)  d2,d3:(m=g+8, same)
    const int g  = lane >> 2;
    const int tc = (lane & 3) << 1;
    const int m_warp = blockIdx.x * 128 + wid * 32;
#pragma unroll
    for (int mt = 0; mt < 2; mt++) {
        int r0 = m_warp + mt * 16 + g;
#pragma unroll
        for (int nt = 0; nt < 16; nt++) {
            int col = nt * 8 + tc;
            if (r0 < N_NODES) {
                unsigned p = f2h2(acc[mt][nt][0], acc[mt][nt][1]);
                *(unsigned*)&g_h[(size_t)r0 * D + col] = p;
            }
            if (r0 + 8 < N_NODES) {
                unsigned p = f2h2(acc[mt][nt][2], acc[mt][nt][3]);
                *(unsigned*)&g_h[(size_t)(r0 + 8) * D + col] = p;
            }
        }
    }
}

// ---------------------------------------------------------------------------
// CSR build
// ---------------------------------------------------------------------------
__global__ void zero_deg_kernel() {
    int i = blockIdx.x * blockDim.x + threadIdx.x;
    if (i < N_NODES) g_deg[i] = 0;
}

// count + record each edge's position within its row (u16, coalesced 8B/thread)
__global__ void count_kernel(const int4* __restrict__ rows4) {
    int t = blockIdx.x * blockDim.x + threadIdx.x;
    if (t < N_EDGES / 4) {
        int4 r = rows4[t];
        ushort4 pos;
        pos.x = (unsigned short)atomicAdd(&g_deg[r.x], 1);
        pos.y = (unsigned short)atomicAdd(&g_deg[r.y], 1);
        pos.z = (unsigned short)atomicAdd(&g_deg[r.z], 1);
        pos.w = (unsigned short)atomicAdd(&g_deg[r.w], 1);
        ((ushort4*)g_epos)[t] = pos;
    }
}

__global__ __launch_bounds__(SCAN_BLK) void scan1_kernel() {
    __shared__ int s[SCAN_BLK];
    int i = blockIdx.x * SCAN_BLK + threadIdx.x;
    int v = (i < N_NODES) ? g_deg[i] : 0;
    s[threadIdx.x] = v;
    __syncthreads();
#pragma unroll
    for (int d = 1; d < SCAN_BLK; d <<= 1) {
        int t = 0;
        if (threadIdx.x >= d) t = s[threadIdx.x - d];
        __syncthreads();
        if (threadIdx.x >= d) s[threadIdx.x] += t;
        __syncthreads();
    }
    if (i < N_NODES) g_off[i] = s[threadIdx.x] - v;
    if (threadIdx.x == SCAN_BLK - 1) g_bsum[blockIdx.x] = s[SCAN_BLK - 1];
}

__global__ __launch_bounds__(128) void scan2_kernel() {
    __shared__ int s[128];
    int i = threadIdx.x;
    int v = (i < NSCAN_BLKS) ? g_bsum[i] : 0;
    s[i] = v;
    __syncthreads();
#pragma unroll
    for (int d = 1; d < 128; d <<= 1) {
        int t = (i >= d) ? s[i - d] : 0;
        __syncthreads();
        s[i] += t;
        __syncthreads();
    }
    if (i < NSCAN_BLKS) g_bsum[i] = s[i] - v;   // exclusive
}

__global__ void scan3_kernel() {
    int i = blockIdx.x * blockDim.x + threadIdx.x;
    if (i < N_NODES) g_off[i] += g_bsum[i / SCAN_BLK];
}

// no atomics: slot = off[row] + epos[edge]
__global__ void fill_kernel(const int4* __restrict__ rows4,
                            const int4* __restrict__ cols4,
                            const float4* __restrict__ vals4) {
    int t = blockIdx.x * blockDim.x + threadIdx.x;
    if (t < N_EDGES / 4) {
        int4    r = rows4[t];
        int4    c = cols4[t];
        float4  v = vals4[t];
        ushort4 p = ((const ushort4*)g_epos)[t];
        g_epair[g_off[r.x] + p.x] = make_int2(c.x, __float_as_int(v.x));
        g_epair[g_off[r.y] + p.y] = make_int2(c.y, __float_as_int(v.y));
        g_epair[g_off[r.z] + p.z] = make_int2(c.z, __float_as_int(v.z));
        g_epair[g_off[r.w] + p.w] = make_int2(c.w, __float_as_int(v.w));
    }
}

// ---------------------------------------------------------------------------
// Aggregate + ReLU: one warp per node; lane handles 4 features (8B fp16 load)
// ---------------------------------------------------------------------------
__device__ __forceinline__ void fma_h4(float4& acc, float v, uint2 raw) {
    float2 lo = __half22float2(*(half2*)&raw.x);
    float2 hi = __half22float2(*(half2*)&raw.y);
    acc.x += v * lo.x;
    acc.y += v * lo.y;
    acc.z += v * hi.x;
    acc.w += v * hi.y;
}

__global__ __launch_bounds__(256) void aggregate_kernel(float* __restrict__ out) {
    int n = blockIdx.x * 8 + (threadIdx.x >> 5);
    if (n >= N_NODES) return;
    int lane = threadIdx.x & 31;

    int s = g_off[n];
    int d = g_deg[n];
    int fofs = lane * 4;

    float4 acc = make_float4(0.f, 0.f, 0.f, 0.f);

    int j = 0;
    for (; j + 4 <= d; j += 4) {
        int2 p0 = g_epair[s + j + 0];
        int2 p1 = g_epair[s + j + 1];
        int2 p2 = g_epair[s + j + 2];
        int2 p3 = g_epair[s + j + 3];
        uint2 h0 = *(const uint2*)&g_h[(size_t)p0.x * D + fofs];
        uint2 h1 = *(const uint2*)&g_h[(size_t)p1.x * D + fofs];
        uint2 h2 = *(const uint2*)&g_h[(size_t)p2.x * D + fofs];
        uint2 h3 = *(const uint2*)&g_h[(size_t)p3.x * D + fofs];
        fma_h4(acc, __int_as_float(p0.y), h0);
        fma_h4(acc, __int_as_float(p1.y), h1);
        fma_h4(acc, __int_as_float(p2.y), h2);
        fma_h4(acc, __int_as_float(p3.y), h3);
    }
    for (; j < d; j++) {
        int2 p = g_epair[s + j];
        uint2 hv = *(const uint2*)&g_h[(size_t)p.x * D + fofs];
        fma_h4(acc, __int_as_float(p.y), hv);
    }

    acc.x = fmaxf(acc.x, 0.f);
    acc.y = fmaxf(acc.y, 0.f);
    acc.z = fmaxf(acc.z, 0.f);
    acc.w = fmaxf(acc.w, 0.f);
    *(float4*)&out[(size_t)n * D + fofs] = acc;
}

// ---------------------------------------------------------------------------
// kernel_launch: dense branch (stream 0) || CSR branch (side stream), join,
// then aggregate. All graph-capturable.
// ---------------------------------------------------------------------------
extern "C" void kernel_launch(void* const* d_in, const int* in_sizes, int n_in,
                              void* d_out, int out_size) {
    const float* x    = (const float*)d_in[0];
    const int*   rows = (const int*)d_in[1];
    const int*   cols = (const int*)d_in[2];
    const float* vals = (const float*)d_in[3];
    const float* W    = (const float*)d_in[4];
    float*       out  = (float*)d_out;

    const int EB4 = (N_EDGES / 4 + 255) / 256;  // 3125
    const int NB  = (N_NODES + 255) / 256;      // 391

    // GEMM needs > 48KB dynamic smem; idempotent, called every time (cheap,
    // host-side only — not part of the captured graph work).
    cudaFuncSetAttribute(gemm_tc_kernel,
                         cudaFuncAttributeMaxDynamicSharedMemorySize,
                         GEMM_SMEM_BYTES);

    static cudaStream_t s_side = nullptr;
    static cudaEvent_t  s_fork = nullptr, s_join = nullptr;
    if (!s_side) {
        cudaStreamCreateWithFlags(&s_side, cudaStreamNonBlocking);
        cudaEventCreateWithFlags(&s_fork, cudaEventDisableTiming);
        cudaEventCreateWithFlags(&s_join, cudaEventDisableTiming);
    }

    cudaEventRecord(s_fork, 0);
    cudaStreamWaitEvent(s_side, s_fork, 0);

    // Dense branch (stream 0)
    gemm_tc_kernel<<<(N_NODES + 127) / 128, 128, GEMM_SMEM_BYTES>>>(x, W);

    // CSR branch (side stream)
    zero_deg_kernel<<<NB, 256, 0, s_side>>>();
    count_kernel<<<EB4, 256, 0, s_side>>>((const int4*)rows);
    scan1_kernel<<<NSCAN_BLKS, SCAN_BLK, 0, s_side>>>();
    scan2_kernel<<<1, 128, 0, s_side>>>();
    scan3_kernel<<<NB, 256, 0, s_side>>>();
    fill_kernel<<<EB4, 256, 0, s_side>>>((const int4*)rows, (const int4*)cols,
                                         (const float4*)vals);

    cudaEventRecord(s_join, s_side);
    cudaStreamWaitEvent(0, s_join, 0);

    aggregate_kernel<<<(N_NODES + 7) / 8, 256>>>(out);
}